// round 8
// baseline (speedup 1.0000x reference)
#include <cuda_runtime.h>

// Problem constants
#define H_   768
#define NCT_ 4096
#define NL_  8921
#define NN_  4
#define NREP 8

// Replicated accumulator scratch (zero-init; finalize re-zeroes each call)
__device__ float g_GR[NREP * 8 * H_];  // lw segment sums, 8 replicas
__device__ float g_ER[NREP * 8 * H_];  // enc chunk sums, 8 replicas
__device__ float g_G[8 * H_];          // reduced (written fresh each call)
__device__ float g_E[8 * H_];
__device__ unsigned int g_count = 0;   // last-arrival counter (reset by finalize)

static constexpr int TILE_ROWS = 8;
static constexpr int NB_LW = (NL_ + TILE_ROWS - 1) / TILE_ROWS;  // 1116
static constexpr int NB_EN = NCT_ / TILE_ROWS;                   // 512
static constexpr int NB = NB_LW + NB_EN;                         // 1628

__device__ __forceinline__ void red_add_v4(float* p, float a, float b, float c, float d) {
    asm volatile("red.global.add.v4.f32 [%0], {%1, %2, %3, %4};"
                 :: "l"(p), "f"(a), "f"(b), "f"(c), "f"(d) : "memory");
}

__global__ __launch_bounds__(192, 8) void fused_kernel(
    const float4* __restrict__ lw4, const float4* __restrict__ enc4,
    const float* __restrict__ lw, const void* __restrict__ ids_raw,
    float* __restrict__ out)
{
    const int t = threadIdx.x;
    const int b = blockIdx.x;

    // ---------------- Phase 1: streaming segment column-sums ----------------
    const float4* src;
    float* dstbase;
    int row0, rend, seg0, seg1, split;

    if (b < NB_LW) {
        row0 = b * TILE_ROWS;
        rend = min(row0 + TILE_ROWS, NL_);
        src = lw4;
        dstbase = g_GR + (b & (NREP - 1)) * (8 * H_);
        const int LB[7] = {1113, 2229, 3344, 4459, 5574, 6689, 7804};
        seg0 = 0; seg1 = 0;
        #pragma unroll
        for (int i = 0; i < 7; i++) {
            seg0 += (row0 >= LB[i]);
            seg1 += (rend - 1 >= LB[i]);
        }
        split = (seg1 == seg0) ? rend : LB[seg0];
    } else {
        int b2 = b - NB_LW;
        row0 = b2 * TILE_ROWS;
        rend = row0 + TILE_ROWS;
        src = enc4;
        dstbase = g_ER + (b & (NREP - 1)) * (8 * H_);
        seg0 = row0 >> 9;   // 512 rows per chunk; 8-row tiles aligned -> no split
        seg1 = seg0;
        split = rend;
    }

    if (split == rend) {
        // Fast path: no boundary in tile (all but 7 of 1628 blocks)
        const float4* p0 = src + (size_t)row0 * (H_ / 4) + t;
        const int nrows = rend - row0;
        float ax = 0.f, ay = 0.f, az = 0.f, aw = 0.f;
        if (nrows == TILE_ROWS) {
            float4 v[TILE_ROWS];
            #pragma unroll
            for (int i = 0; i < TILE_ROWS; i++)
                v[i] = __ldg(p0 + i * (H_ / 4));
            #pragma unroll
            for (int i = 0; i < TILE_ROWS; i++) {
                ax += v[i].x; ay += v[i].y; az += v[i].z; aw += v[i].w;
            }
        } else {
            for (int i = 0; i < nrows; i++) {
                float4 x = __ldg(p0 + i * (H_ / 4));
                ax += x.x; ay += x.y; az += x.z; aw += x.w;
            }
        }
        red_add_v4(dstbase + seg0 * H_ + t * 4, ax, ay, az, aw);
    } else {
        // Boundary tile: two partial sums
        float ax = 0.f, ay = 0.f, az = 0.f, aw = 0.f;
        int r = row0;
        for (; r < split; ++r) {
            float4 x = __ldg(&src[(size_t)r * (H_ / 4) + t]);
            ax += x.x; ay += x.y; az += x.z; aw += x.w;
        }
        red_add_v4(dstbase + seg0 * H_ + t * 4, ax, ay, az, aw);
        ax = ay = az = aw = 0.f;
        for (; r < rend; ++r) {
            float4 x = __ldg(&src[(size_t)r * (H_ / 4) + t]);
            ax += x.x; ay += x.y; az += x.z; aw += x.w;
        }
        red_add_v4(dstbase + seg1 * H_ + t * 4, ax, ay, az, aw);
    }

    // ---------------- Last-arrival gate ----------------
    __threadfence();
    __shared__ bool is_last;
    if (t == 0)
        is_last = (atomicAdd(&g_count, 1u) == (unsigned)(gridDim.x - 1));
    __syncthreads();
    if (!is_last) return;
    __threadfence();  // acquire accumulators published by other blocks

    // ------------- Phase 2a: replica reduction (one block, float4) ----------
    {
        const float4* gr4 = (const float4*)g_GR;
        const float4* er4 = (const float4*)g_ER;
        float4* g4 = (float4*)g_G;
        float4* e4 = (float4*)g_E;
        #pragma unroll
        for (int jj = 0; jj < (8 * H_ / 4) / 192; jj++) {   // 8 iters
            int j = t + jj * 192;
            float4 sg = gr4[j], se = er4[j];
            #pragma unroll
            for (int r = 1; r < NREP; r++) {
                float4 a = gr4[r * (8 * H_ / 4) + j];
                float4 c = er4[r * (8 * H_ / 4) + j];
                sg.x += a.x; sg.y += a.y; sg.z += a.z; sg.w += a.w;
                se.x += c.x; se.y += c.y; se.z += c.z; se.w += c.w;
            }
            g4[j] = sg;
            e4[j] = se;
        }
    }
    __syncthreads();

    // ------------- Phase 2b: finalize ---------------------------------------
    // note_end_chunk_ids: detect int64 vs int32 (values small nonneg, sorted)
    const int* i32 = (const int*)ids_raw;
    int id0, id1, id2, id3;
    if (i32[1] == 0 && i32[3] == 0) {            // int64 layout
        const long long* i64 = (const long long*)ids_raw;
        id0 = (int)i64[0]; id1 = (int)i64[1]; id2 = (int)i64[2]; id3 = (int)i64[3];
    } else {
        id0 = i32[0]; id1 = i32[1]; id2 = i32[2]; id3 = i32[3];
    }

    // w(n,c): softmax over notes of the 0/-1e9 mask, chunk-piecewise
    __shared__ float s_wn[NN_][8];
    if (t < 32) {
        int c = t & 7, n = t >> 3;
        int k = (id0 < c) + (id1 < c) + (id2 < c) + (id3 < c);
        int idn = (n == 0) ? id0 : (n == 1) ? id1 : (n == 2) ? id2 : id3;
        s_wn[n][c] = (k == 0) ? 0.25f : ((idn < c) ? (1.0f / (float)k) : 0.0f);
    }
    __syncthreads();

    const int SL[15] = {1113,1114,1115, 2229,2230, 3344,3345, 4459,4460,
                        5574,5575, 6689,6690, 7804,7805};
    const int SC[15] = {0,0,0, 1,1, 2,2, 3,3, 4,4, 5,5, 6,6};
    const int SM[15] = {8,8,1, 8,2, 8,3, 8,4, 8,5, 8,6, 8,7};

    for (int hh = 0; hh < H_ / 192; hh++) {
        const int h = t + hh * 192;

        float Pm[9];
        Pm[0] = 0.0f;
        #pragma unroll
        for (int m = 1; m <= 8; m++) Pm[m] = Pm[m - 1] + g_E[(m - 1) * H_ + h];
        const float Ptot = Pm[8];

        for (int n = 0; n < NN_; n++) {
            float gacc = 0.0f;
            #pragma unroll
            for (int c = 0; c < 8; c++) gacc += s_wn[n][c] * g_G[c * H_ + h];
            float score = Ptot * gacc;
            #pragma unroll
            for (int j = 0; j < 15; j++) {
                float d = s_wn[n][SC[j]] - s_wn[n][SC[j] + 1];
                score += d * __ldg(&lw[SL[j] * H_ + h]) * Pm[SM[j]];
            }
            out[n * H_ + h] = 1.0f / (1.0f + expf(-score));
        }
    }

    // ------------- Restore state for the next graph replay ------------------
    __syncthreads();
    {
        float4 z = make_float4(0.f, 0.f, 0.f, 0.f);
        float4* gr4 = (float4*)g_GR;
        float4* er4 = (float4*)g_ER;
        for (int j = t; j < NREP * (8 * H_ / 4); j += 192) {
            gr4[j] = z;
            er4[j] = z;
        }
    }
    if (t == 0) g_count = 0;
}

extern "C" void kernel_launch(void* const* d_in, const int* in_sizes, int n_in,
                              void* d_out, int out_size) {
    const float* encoding      = (const float*)d_in[0];
    // d_in[1] = label_queries: provably unused (softmax over notes cancels it)
    const float* label_weights = (const float*)d_in[2];
    const void*  ids           = d_in[3];
    float* out = (float*)d_out;

    fused_kernel<<<NB, 192>>>((const float4*)label_weights,
                              (const float4*)encoding,
                              label_weights, ids, out);
}

// round 11
// speedup vs baseline: 1.6334x; 1.6334x over previous
#include <cuda_runtime.h>
#include <cstdint>

// Problem constants
#define H_   768
#define NCT_ 4096
#define NL_  8921
#define NN_  4

// Self-restoring accumulator scratch (zero-init; finalize re-zeroes each call)
__device__ float g_G[8 * H_];          // column sums of reshaped label_weights per l-group
__device__ float g_E[8 * H_];          // per-chunk column sums of encoding
__device__ unsigned int g_count = 0;   // last-arrival counter (reset by finalize)

static constexpr int TILE_ROWS = 10;
static constexpr int ROW_BYTES = H_ * 4;                  // 3072
static constexpr int ROW_F4 = H_ / 4;                     // 192
static constexpr int TILE_BYTES = TILE_ROWS * ROW_BYTES;  // 30720 (30 KB dynamic)
static constexpr int NB_LW = (NL_ + TILE_ROWS - 1) / TILE_ROWS;   // 893
static constexpr int NB_EN = (NCT_ + TILE_ROWS - 1) / TILE_ROWS;  // 410
static constexpr int NB = NB_LW + NB_EN;                          // 1303

__device__ __forceinline__ uint32_t smem_u32(const void* p) {
    return (uint32_t)__cvta_generic_to_shared(p);
}
__device__ __forceinline__ void red_add_v4(float* p, float a, float b, float c, float d) {
    asm volatile("red.global.add.v4.f32 [%0], {%1, %2, %3, %4};"
                 :: "l"(p), "f"(a), "f"(b), "f"(c), "f"(d) : "memory");
}

__global__ __launch_bounds__(192, 6) void fused_kernel(
    const char* __restrict__ lw_bytes, const char* __restrict__ enc_bytes,
    const float* __restrict__ lw, const void* __restrict__ ids_raw,
    float* __restrict__ out)
{
    extern __shared__ __align__(16) float4 s_tile[];   // TILE_BYTES dynamic
    __shared__ __align__(8) unsigned long long s_mbar;
    __shared__ bool is_last;

    const int t = threadIdx.x;
    const int b = blockIdx.x;

    // ---------------- Tile geometry (at most ONE segment boundary per tile) --
    const char* src;
    float* dst;
    int row0, nrows, seg0, seg1, split_local;
    if (b < NB_LW) {
        row0 = b * TILE_ROWS;
        int rend = min(row0 + TILE_ROWS, NL_);
        nrows = rend - row0;
        src = lw_bytes; dst = g_G;
        const int LB[7] = {1113, 2229, 3344, 4459, 5574, 6689, 7804};
        seg0 = 0; seg1 = 0;
        #pragma unroll
        for (int i = 0; i < 7; i++) {
            seg0 += (row0 >= LB[i]);
            seg1 += (rend - 1 >= LB[i]);
        }
        split_local = (seg0 == seg1) ? nrows : (LB[seg0] - row0);
    } else {
        row0 = (b - NB_LW) * TILE_ROWS;
        int rend = min(row0 + TILE_ROWS, NCT_);
        nrows = rend - row0;
        src = enc_bytes; dst = g_E;
        seg0 = row0 >> 9;              // 512 rows per chunk
        seg1 = (rend - 1) >> 9;
        split_local = (seg0 == seg1) ? nrows : (((seg0 + 1) << 9) - row0);
    }
    const unsigned bytes = (unsigned)nrows * ROW_BYTES;

    // ---------------- Phase 1: TMA 1D bulk load of the tile ----------------
    const uint32_t mbar = smem_u32(&s_mbar);
    if (t == 0) {
        asm volatile("mbarrier.init.shared.b64 [%0], %1;" :: "r"(mbar), "r"(1) : "memory");
        asm volatile("fence.proxy.async.shared::cta;" ::: "memory");
    }
    __syncthreads();
    if (t == 0) {
        asm volatile("mbarrier.arrive.expect_tx.shared.b64 _, [%0], %1;"
                     :: "r"(mbar), "r"(bytes) : "memory");
        // Canonical sm_90+ 1D bulk form (shared::cluster dst == own CTA at cluster size 1)
        asm volatile(
            "cp.async.bulk.shared::cluster.global.mbarrier::complete_tx::bytes "
            "[%0], [%1], %2, [%3];"
            :: "r"(smem_u32(s_tile)), "l"(src + (size_t)row0 * ROW_BYTES),
               "r"(bytes), "r"(mbar) : "memory");
    }
    // Wait, parity 0 (acquire — generic LDS follows)
    {
        uint32_t done;
        asm volatile(
            "{\n\t.reg .pred p;\n\t"
            "mbarrier.try_wait.parity.acquire.cta.shared::cta.b64 p, [%1], %2;\n\t"
            "selp.b32 %0, 1, 0, p;\n\t}"
            : "=r"(done) : "r"(mbar), "r"(0u) : "memory");
        if (!done) {
            asm volatile(
                "{\n\t.reg .pred P1;\n\t"
                "WAIT_LOOP_%=:\n\t"
                "mbarrier.try_wait.parity.acquire.cta.shared::cta.b64 P1, [%0], %1, 0x989680;\n\t"
                "@P1 bra.uni WAIT_DONE_%=;\n\t"
                "bra.uni WAIT_LOOP_%=;\n\t"
                "WAIT_DONE_%=:\n\t}"
                :: "r"(mbar), "r"(0u) : "memory");
        }
    }

    // ---------------- Reduce tile columns from SMEM ----------------
    {
        float ax = 0.f, ay = 0.f, az = 0.f, aw = 0.f;
        int r = 0;
        for (; r < split_local; ++r) {
            float4 v = s_tile[r * ROW_F4 + t];
            ax += v.x; ay += v.y; az += v.z; aw += v.w;
        }
        red_add_v4(dst + seg0 * H_ + t * 4, ax, ay, az, aw);
        if (r < nrows) {
            ax = ay = az = aw = 0.f;
            for (; r < nrows; ++r) {
                float4 v = s_tile[r * ROW_F4 + t];
                ax += v.x; ay += v.y; az += v.z; aw += v.w;
            }
            red_add_v4(dst + seg1 * H_ + t * 4, ax, ay, az, aw);
        }
    }

    // ---------------- Last-arrival gate ----------------
    __threadfence();
    if (t == 0)
        is_last = (atomicAdd(&g_count, 1u) == (unsigned)(gridDim.x - 1));
    __syncthreads();
    if (!is_last) return;
    __threadfence();  // acquire accumulators published by other blocks

    // ---------------- Phase 2: finalize (ONE block; compact, L2-fed) -------
    // note_end_chunk_ids: detect int64 vs int32 (values small nonneg, sorted)
    const int* i32 = (const int*)ids_raw;
    int id0, id1, id2, id3;
    if (i32[1] == 0 && i32[3] == 0) {            // int64 layout
        const long long* i64 = (const long long*)ids_raw;
        id0 = (int)i64[0]; id1 = (int)i64[1]; id2 = (int)i64[2]; id3 = (int)i64[3];
    } else {
        id0 = i32[0]; id1 = i32[1]; id2 = i32[2]; id3 = i32[3];
    }

    // w(n,c): softmax over notes of the 0/-1e9 mask, chunk-piecewise
    __shared__ float s_wn[NN_][8];
    if (t < 32) {
        int c = t & 7, n = t >> 3;
        int k = (id0 < c) + (id1 < c) + (id2 < c) + (id3 < c);
        int idn = (n == 0) ? id0 : (n == 1) ? id1 : (n == 2) ? id2 : id3;
        s_wn[n][c] = (k == 0) ? 0.25f : ((idn < c) ? (1.0f / (float)k) : 0.0f);
    }
    __syncthreads();

    const int SL[15] = {1113,1114,1115, 2229,2230, 3344,3345, 4459,4460,
                        5574,5575, 6689,6690, 7804,7805};
    const int SC[15] = {0,0,0, 1,1, 2,2, 3,3, 4,4, 5,5, 6,6};
    const int SM[15] = {8,8,1, 8,2, 8,3, 8,4, 8,5, 8,6, 8,7};

    for (int hh = 0; hh < H_ / 192; hh++) {
        const int h = t + hh * 192;

        float Pm[9];
        Pm[0] = 0.0f;
        #pragma unroll
        for (int m = 1; m <= 8; m++) Pm[m] = Pm[m - 1] + g_E[(m - 1) * H_ + h];
        const float Ptot = Pm[8];

        for (int n = 0; n < NN_; n++) {
            float gacc = 0.0f;
            #pragma unroll
            for (int c = 0; c < 8; c++) gacc += s_wn[n][c] * g_G[c * H_ + h];
            float score = Ptot * gacc;
            #pragma unroll
            for (int j = 0; j < 15; j++) {
                float d = s_wn[n][SC[j]] - s_wn[n][SC[j] + 1];
                score += d * __ldg(&lw[SL[j] * H_ + h]) * Pm[SM[j]];
            }
            out[n * H_ + h] = 1.0f / (1.0f + expf(-score));
        }
    }

    // ---------------- Restore state for the next graph replay ----------------
    __syncthreads();
    {
        float4 z = make_float4(0.f, 0.f, 0.f, 0.f);
        float4* g4 = (float4*)g_G;
        float4* e4 = (float4*)g_E;
        #pragma unroll
        for (int jj = 0; jj < (8 * H_ / 4) / 192; jj++) {   // 8 iters
            g4[t + jj * 192] = z;
            e4[t + jj * 192] = z;
        }
    }
    if (t == 0) g_count = 0;
}

extern "C" void kernel_launch(void* const* d_in, const int* in_sizes, int n_in,
                              void* d_out, int out_size) {
    const float* encoding      = (const float*)d_in[0];
    // d_in[1] = label_queries: provably unused (softmax over notes cancels it)
    const float* label_weights = (const float*)d_in[2];
    const void*  ids           = d_in[3];
    float* out = (float*)d_out;

    fused_kernel<<<NB, 192, TILE_BYTES>>>((const char*)label_weights,
                                          (const char*)encoding,
                                          label_weights, ids, out);
}

// round 13
// speedup vs baseline: 2.5725x; 1.5749x over previous
#include <cuda_runtime.h>
#include <cstdint>

// Problem constants
#define H_   768
#define NCT_ 4096
#define NL_  8921
#define NN_  4

// Self-restoring accumulator scratch (zero-init at load; finalize re-zeroes)
__device__ float g_G[8 * H_];   // column sums of reshaped label_weights per l-group
__device__ float g_E[8 * H_];   // per-chunk column sums of encoding

static constexpr int TILE_ROWS = 32;
static constexpr int NB_LW = (NL_ + TILE_ROWS - 1) / TILE_ROWS;  // 279
static constexpr int NB_EN = NCT_ / TILE_ROWS;                   // 128
static constexpr int NB = NB_LW + NB_EN;                         // 407

__device__ __forceinline__ void red_add_v4(float* p, float a, float b, float c, float d) {
    asm volatile("red.global.add.v4.f32 [%0], {%1, %2, %3, %4};"
                 :: "l"(p), "f"(a), "f"(b), "f"(c), "f"(d) : "memory");
}

// ---------------- Kernel 1: streaming segment column-sums ----------------
__global__ __launch_bounds__(192, 8) void reduce_kernel(
    const float4* __restrict__ lw4, const float4* __restrict__ enc4)
{
    const int t = threadIdx.x;
    const int b = blockIdx.x;

    const float4* src;
    float* dst;
    int row0, rend, seg0, seg1, split;

    if (b < NB_LW) {
        row0 = b * TILE_ROWS;
        rend = min(row0 + TILE_ROWS, NL_);
        src = lw4; dst = g_G;
        const int LB[7] = {1113, 2229, 3344, 4459, 5574, 6689, 7804};
        seg0 = 0; seg1 = 0;
        #pragma unroll
        for (int i = 0; i < 7; i++) {
            seg0 += (row0 >= LB[i]);
            seg1 += (rend - 1 >= LB[i]);
        }
        split = (seg0 == seg1) ? rend : LB[seg0];
    } else {
        int b2 = b - NB_LW;
        row0 = b2 * TILE_ROWS;
        rend = row0 + TILE_ROWS;
        src = enc4; dst = g_E;
        seg0 = row0 >> 9;   // 512 rows per chunk; 32-row tiles aligned -> no split
        seg1 = seg0;
        split = rend;
    }

    float ax = 0.f, ay = 0.f, az = 0.f, aw = 0.f;
    int r = row0;
    // First segment: batch loads 8-deep for MLP, then accumulate.
    while (r + 8 <= split) {
        float4 v[8];
        #pragma unroll
        for (int i = 0; i < 8; i++)
            v[i] = __ldg(&src[(size_t)(r + i) * (H_ / 4) + t]);
        #pragma unroll
        for (int i = 0; i < 8; i++) {
            ax += v[i].x; ay += v[i].y; az += v[i].z; aw += v[i].w;
        }
        r += 8;
    }
    for (; r < split; ++r) {
        float4 v = __ldg(&src[(size_t)r * (H_ / 4) + t]);
        ax += v.x; ay += v.y; az += v.z; aw += v.w;
    }
    red_add_v4(dst + seg0 * H_ + t * 4, ax, ay, az, aw);

    if (r < rend) {   // rare: tile straddles one segment boundary
        ax = ay = az = aw = 0.f;
        while (r + 8 <= rend) {
            float4 v[8];
            #pragma unroll
            for (int i = 0; i < 8; i++)
                v[i] = __ldg(&src[(size_t)(r + i) * (H_ / 4) + t]);
            #pragma unroll
            for (int i = 0; i < 8; i++) {
                ax += v[i].x; ay += v[i].y; az += v[i].z; aw += v[i].w;
            }
            r += 8;
        }
        for (; r < rend; ++r) {
            float4 v = __ldg(&src[(size_t)r * (H_ / 4) + t]);
            ax += v.x; ay += v.y; az += v.z; aw += v.w;
        }
        red_add_v4(dst + seg1 * H_ + t * 4, ax, ay, az, aw);
    }
}

// ------------- Kernel 2: finalize (ONE block, 768 threads) + restore -------
__global__ __launch_bounds__(768) void finalize_kernel(
    const float* __restrict__ lw, const void* __restrict__ ids_raw,
    float* __restrict__ out)
{
    const int t = threadIdx.x;   // = h
    const int h = t;

    // note_end_chunk_ids: detect int64 vs int32 (values small nonneg, sorted)
    const int* i32 = (const int*)ids_raw;
    int id0, id1, id2, id3;
    if (i32[1] == 0 && i32[3] == 0) {            // int64 layout
        const long long* i64 = (const long long*)ids_raw;
        id0 = (int)i64[0]; id1 = (int)i64[1]; id2 = (int)i64[2]; id3 = (int)i64[3];
    } else {
        id0 = i32[0]; id1 = i32[1]; id2 = i32[2]; id3 = i32[3];
    }

    // w(n,c): softmax over notes of the 0/-1e9 mask, chunk-piecewise
    __shared__ float s_wn[NN_][8];
    if (t < 32) {
        int c = t & 7, n = t >> 3;
        int k = (id0 < c) + (id1 < c) + (id2 < c) + (id3 < c);
        int idn = (n == 0) ? id0 : (n == 1) ? id1 : (n == 2) ? id2 : id3;
        s_wn[n][c] = (k == 0) ? 0.25f : ((idn < c) ? (1.0f / (float)k) : 0.0f);
    }
    __syncthreads();

    const int SL[15] = {1113,1114,1115, 2229,2230, 3344,3345, 4459,4460,
                        5574,5575, 6689,6690, 7804,7805};
    const int SC[15] = {0,0,0, 1,1, 2,2, 3,3, 4,4, 5,5, 6,6};
    const int SM[15] = {8,8,1, 8,2, 8,3, 8,4, 8,5, 8,6, 8,7};

    // Gather everything for this h once (L2-resident g_*, 15 DRAM lw rows)
    float LWv[15];
    #pragma unroll
    for (int j = 0; j < 15; j++) LWv[j] = __ldg(&lw[SL[j] * H_ + h]);

    float Pm[9];
    Pm[0] = 0.0f;
    #pragma unroll
    for (int m = 1; m <= 8; m++) Pm[m] = Pm[m - 1] + g_E[(m - 1) * H_ + h];
    const float Ptot = Pm[8];

    float Gc[8];
    #pragma unroll
    for (int c = 0; c < 8; c++) Gc[c] = g_G[c * H_ + h];

    #pragma unroll
    for (int n = 0; n < NN_; n++) {
        float gacc = 0.0f;
        #pragma unroll
        for (int c = 0; c < 8; c++) gacc += s_wn[n][c] * Gc[c];
        float score = Ptot * gacc;
        #pragma unroll
        for (int j = 0; j < 15; j++) {
            float d = s_wn[n][SC[j]] - s_wn[n][SC[j] + 1];
            score += d * LWv[j] * Pm[SM[j]];
        }
        out[n * H_ + h] = 1.0f / (1.0f + expf(-score));
    }

    // Restore accumulators for the next graph replay (values already consumed)
    __syncthreads();
    {
        float4 z = make_float4(0.f, 0.f, 0.f, 0.f);
        float4* g4 = (float4*)g_G;
        float4* e4 = (float4*)g_E;
        #pragma unroll
        for (int jj = 0; jj < (8 * H_ / 4) / 768; jj++) {   // 2 iters
            g4[t + jj * 768] = z;
            e4[t + jj * 768] = z;
        }
    }
}

extern "C" void kernel_launch(void* const* d_in, const int* in_sizes, int n_in,
                              void* d_out, int out_size) {
    const float* encoding      = (const float*)d_in[0];
    // d_in[1] = label_queries: provably unused (softmax over notes cancels it)
    const float* label_weights = (const float*)d_in[2];
    const void*  ids           = d_in[3];
    float* out = (float*)d_out;

    reduce_kernel<<<NB, 192>>>((const float4*)label_weights,
                               (const float4*)encoding);
    finalize_kernel<<<1, 768>>>(label_weights, ids, out);
}

// round 14
// speedup vs baseline: 2.6175x; 1.0175x over previous
#include <cuda_runtime.h>
#include <cstdint>

// Problem constants
#define H_   768
#define NCT_ 4096
#define NL_  8921
#define NN_  4

// Self-restoring accumulator scratch (zero-init at load; finalize re-zeroes)
__device__ float g_G[8 * H_];   // column sums of reshaped label_weights per l-group
__device__ float g_E[8 * H_];   // per-chunk column sums of encoding

static constexpr int TILE_ROWS = 16;
static constexpr int NB_LW = (NL_ + TILE_ROWS - 1) / TILE_ROWS;  // 558
static constexpr int NB_EN = NCT_ / TILE_ROWS;                   // 256
static constexpr int NB = NB_LW + NB_EN;                         // 814

__device__ __forceinline__ void red_add_v4(float* p, float a, float b, float c, float d) {
    asm volatile("red.global.add.v4.f32 [%0], {%1, %2, %3, %4};"
                 :: "l"(p), "f"(a), "f"(b), "f"(c), "f"(d) : "memory");
}

// ---------------- Kernel 1: streaming segment column-sums ----------------
__global__ __launch_bounds__(192, 8) void reduce_kernel(
    const float4* __restrict__ lw4, const float4* __restrict__ enc4)
{
    const int t = threadIdx.x;
    const int b = blockIdx.x;

    const float4* src;
    float* dst;
    int row0, rend, seg0, seg1, split;

    if (b < NB_LW) {
        row0 = b * TILE_ROWS;
        rend = min(row0 + TILE_ROWS, NL_);
        src = lw4; dst = g_G;
        const int LB[7] = {1113, 2229, 3344, 4459, 5574, 6689, 7804};
        seg0 = 0; seg1 = 0;
        #pragma unroll
        for (int i = 0; i < 7; i++) {
            seg0 += (row0 >= LB[i]);
            seg1 += (rend - 1 >= LB[i]);
        }
        split = (seg0 == seg1) ? rend : LB[seg0];
    } else {
        int b2 = b - NB_LW;
        row0 = b2 * TILE_ROWS;
        rend = row0 + TILE_ROWS;
        src = enc4; dst = g_E;
        seg0 = row0 >> 9;   // 512 rows per chunk; 16-row tiles aligned -> no split
        seg1 = seg0;
        split = rend;
    }

    float ax = 0.f, ay = 0.f, az = 0.f, aw = 0.f;
    int r = row0;
    // First segment: batch loads 8-deep for MLP, then accumulate.
    while (r + 8 <= split) {
        float4 v[8];
        #pragma unroll
        for (int i = 0; i < 8; i++)
            v[i] = __ldg(&src[(size_t)(r + i) * (H_ / 4) + t]);
        #pragma unroll
        for (int i = 0; i < 8; i++) {
            ax += v[i].x; ay += v[i].y; az += v[i].z; aw += v[i].w;
        }
        r += 8;
    }
    for (; r < split; ++r) {
        float4 v = __ldg(&src[(size_t)r * (H_ / 4) + t]);
        ax += v.x; ay += v.y; az += v.z; aw += v.w;
    }
    red_add_v4(dst + seg0 * H_ + t * 4, ax, ay, az, aw);

    if (r < rend) {   // rare: tile straddles one segment boundary
        ax = ay = az = aw = 0.f;
        while (r + 8 <= rend) {
            float4 v[8];
            #pragma unroll
            for (int i = 0; i < 8; i++)
                v[i] = __ldg(&src[(size_t)(r + i) * (H_ / 4) + t]);
            #pragma unroll
            for (int i = 0; i < 8; i++) {
                ax += v[i].x; ay += v[i].y; az += v[i].z; aw += v[i].w;
            }
            r += 8;
        }
        for (; r < rend; ++r) {
            float4 v = __ldg(&src[(size_t)r * (H_ / 4) + t]);
            ax += v.x; ay += v.y; az += v.z; aw += v.w;
        }
        red_add_v4(dst + seg1 * H_ + t * 4, ax, ay, az, aw);
    }
}

// ------ Kernel 2: finalize (4 blocks, one per note) + distributed restore ------
__global__ __launch_bounds__(768) void finalize_kernel(
    const float* __restrict__ lw, const void* __restrict__ ids_raw,
    float* __restrict__ out)
{
    const int t = threadIdx.x;   // = h
    const int h = t;
    const int n = blockIdx.x;    // note index

    // note_end_chunk_ids: detect int64 vs int32 (values small nonneg, sorted)
    const int* i32 = (const int*)ids_raw;
    int id0, id1, id2, id3;
    if (i32[1] == 0 && i32[3] == 0) {            // int64 layout
        const long long* i64 = (const long long*)ids_raw;
        id0 = (int)i64[0]; id1 = (int)i64[1]; id2 = (int)i64[2]; id3 = (int)i64[3];
    } else {
        id0 = i32[0]; id1 = i32[1]; id2 = i32[2]; id3 = i32[3];
    }
    const int idn = (n == 0) ? id0 : (n == 1) ? id1 : (n == 2) ? id2 : id3;

    // w(n,c): softmax over notes of the 0/-1e9 mask, chunk-piecewise
    float wn[9];   // wn[8] pad for SC[j]+1 access pattern safety (c<8 used)
    #pragma unroll
    for (int c = 0; c < 8; c++) {
        int k = (id0 < c) + (id1 < c) + (id2 < c) + (id3 < c);
        wn[c] = (k == 0) ? 0.25f : ((idn < c) ? (1.0f / (float)k) : 0.0f);
    }
    wn[8] = 0.f;

    const int SL[15] = {1113,1114,1115, 2229,2230, 3344,3345, 4459,4460,
                        5574,5575, 6689,6690, 7804,7805};
    const int SC[15] = {0,0,0, 1,1, 2,2, 3,3, 4,4, 5,5, 6,6};
    const int SM[15] = {8,8,1, 8,2, 8,3, 8,4, 8,5, 8,6, 8,7};

    // Gather everything for this h (independent loads; L2-resident in wall run)
    float LWv[15];
    #pragma unroll
    for (int j = 0; j < 15; j++) LWv[j] = __ldg(&lw[SL[j] * H_ + h]);

    float Pm[9];
    Pm[0] = 0.0f;
    #pragma unroll
    for (int m = 1; m <= 8; m++) Pm[m] = Pm[m - 1] + g_E[(m - 1) * H_ + h];
    const float Ptot = Pm[8];

    float gacc = 0.0f;
    #pragma unroll
    for (int c = 0; c < 8; c++) gacc += wn[c] * g_G[c * H_ + h];
    float score = Ptot * gacc;
    #pragma unroll
    for (int j = 0; j < 15; j++) {
        float d = wn[SC[j]] - wn[SC[j] + 1];
        score += d * LWv[j] * Pm[SM[j]];
    }
    out[n * H_ + h] = 1.0f / (1.0f + expf(-score));

    // Restore accumulators for the next graph replay. Each of the 4 blocks
    // zeroes a disjoint quarter AFTER all blocks' reads... blocks are
    // independent: block n zeroes the quarter only it is responsible for —
    // but other blocks also read all of g_G/g_E. Safe ordering: every block
    // reads before any block's writes land? Not guaranteed. Instead: each
    // block re-zeroes only after a grid-wide "all reads done" signal would be
    // needed. Avoid the hazard entirely: all 4 blocks write the SAME zeros to
    // the full arrays — writes are idempotent, so ordering vs other blocks'
    // reads matters. Solution: reads above loaded into registers already
    // (g_E into Pm, g_G into gacc) BEFORE this point in program order, and
    // __syncthreads ensures block-local completion. Cross-block: another
    // block may still be reading while we zero. Guard with a store only from
    // block that arrives last via atomic ticket.
    __syncthreads();
    __shared__ bool s_last;
    __threadfence();
    if (t == 0) {
        __device__ static unsigned int g_fin;   // zero-init
        s_last = (atomicAdd(&g_fin, 1u) == NN_ - 1);
        if (s_last) atomicExch(&g_fin, 0u);
    }
    __syncthreads();
    if (s_last) {
        float4 z = make_float4(0.f, 0.f, 0.f, 0.f);
        float4* g4 = (float4*)g_G;
        float4* e4 = (float4*)g_E;
        #pragma unroll
        for (int jj = 0; jj < (8 * H_ / 4) / 768; jj++) {   // 2 iters
            g4[t + jj * 768] = z;
            e4[t + jj * 768] = z;
        }
    }
}

extern "C" void kernel_launch(void* const* d_in, const int* in_sizes, int n_in,
                              void* d_out, int out_size) {
    const float* encoding      = (const float*)d_in[0];
    // d_in[1] = label_queries: provably unused (softmax over notes cancels it)
    const float* label_weights = (const float*)d_in[2];
    const void*  ids           = d_in[3];
    float* out = (float*)d_out;

    reduce_kernel<<<NB, 192>>>((const float4*)label_weights,
                               (const float4*)encoding);
    finalize_kernel<<<NN_, 768>>>(label_weights, ids, out);
}